// round 13
// baseline (speedup 1.0000x reference)
#include <cuda_runtime.h>

typedef unsigned long long u64;
typedef unsigned int u32;

__device__ __forceinline__ u64 pack2(float lo, float hi) {
    u64 r; asm("mov.b64 %0,{%1,%2};" : "=l"(r) : "f"(lo), "f"(hi)); return r;
}
__device__ __forceinline__ void unpack2(u64 v, float& lo, float& hi) {
    asm("mov.b64 {%0,%1}, %2;" : "=f"(lo), "=f"(hi) : "l"(v));
}
__device__ __forceinline__ u64 fma2(u64 a, u64 b, u64 c) {
    u64 d; asm("fma.rn.f32x2 %0,%1,%2,%3;" : "=l"(d) : "l"(a), "l"(b), "l"(c)); return d;
}
__device__ __forceinline__ u64 add2(u64 a, u64 b) {
    u64 d; asm("add.rn.f32x2 %0,%1,%2;" : "=l"(d) : "l"(a), "l"(b)); return d;
}
__device__ __forceinline__ u64 mul2(u64 a, u64 b) {
    u64 d; asm("mul.rn.f32x2 %0,%1,%2;" : "=l"(d) : "l"(a), "l"(b)); return d;
}
__device__ __forceinline__ float sqrt_approx(float x) {
    float r; asm("sqrt.approx.f32 %0, %1;" : "=f"(r) : "f"(x)); return r;
}
// relu both halves of a packed f32x2 (2 scalar FMNMX, alu pipe)
__device__ __forceinline__ u64 relu2(u64 v) {
    float lo, hi; unpack2(v, lo, hi);
    return pack2(fmaxf(lo, 0.f), fmaxf(hi, 0.f));
}
// warp-broadcast a packed u64 from lane src (2 x shfl.b32)
__device__ __forceinline__ u64 shfl2(u64 v, int src) {
    u32 lo, hi;
    asm("mov.b64 {%0,%1}, %2;" : "=r"(lo), "=r"(hi) : "l"(v));
    lo = __shfl_sync(0xffffffffu, lo, src);
    hi = __shfl_sync(0xffffffffu, hi, src);
    u64 r; asm("mov.b64 %0,{%1,%2};" : "=l"(r) : "r"(lo), "r"(hi));
    return r;
}

constexpr int NE = 7;      // entities
constexpr int DE = 4;      // dims per entity
constexpr int H  = 128;    // half embedding
constexpr int NPAIR = 21;  // unordered pairs
constexpr int OUTC = 2 * H;
constexpr int ROW = NE * OUTC;   // floats per batch element in out
constexpr int GRID = 592;        // 148 SMs x 4 resident CTAs = one wave

// pair index tables packed 3 bits/entry into u64 immediates.
// (namespace-scope arrays are used ONLY inside this constant expression —
//  never odr-used from device code, which was the R12 compile failure.)
constexpr u64 pack_idx(const int* a) {
    u64 r = 0;
    for (int p = 0; p < NPAIR; p++) r |= (u64)a[p] << (3 * p);
    return r;
}
constexpr int PIa_host[NPAIR] = {0,0,0,0,0,0,1,1,1,1,1,2,2,2,2,3,3,3,4,4,5};
constexpr int PJa_host[NPAIR] = {1,2,3,4,5,6,2,3,4,5,6,3,4,5,6,4,5,6,5,6,6};
constexpr u64 PIp = pack_idx(PIa_host);
constexpr u64 PJp = pack_idx(PJa_host);

__global__ __launch_bounds__(256, 4)
void enc_kernel(const float* __restrict__ ctx,
                const float* __restrict__ w_prop, const float* __restrict__ b_prop,
                const float* __restrict__ w_rel,  const float* __restrict__ b_rel,
                float* __restrict__ out, int B, int G)
{
    // kernel-local pair tables for the fully-unrolled loop (fold to immediates)
    constexpr int PI[NPAIR] = {0,0,0,0,0,0,1,1,1,1,1,2,2,2,2,3,3,3,4,4,5};
    constexpr int PJ[NPAIR] = {1,2,3,4,5,6,2,3,4,5,6,3,4,5,6,4,5,6,5,6,6};

    // NO shared memory, NO barriers: each warp is fully independent.
    // CTA = 8 warps = 2 sub-blocks of 4 warps; sub-block owns one batch pair.
    const int tid  = threadIdx.x;
    const int lane = tid & 31;
    const int wid  = tid >> 5;
    const int sub  = wid >> 2;                // 0/1: which batch pair
    const int h    = (wid & 3) * 32 + lane;   // output column 0..127

    // weights broadcast-packed once per CTA (persistent loop amortizes)
    u64 wp2[DE], wr2[DE + 1], bp2, br2;
    #pragma unroll
    for (int d = 0; d < DE; d++)     { float w = w_prop[d * H + h]; wp2[d] = pack2(w, w); }
    #pragma unroll
    for (int d = 0; d < DE + 1; d++) { float w = w_rel [d * H + h]; wr2[d] = pack2(w, w); }
    { float b = b_prop[h]; bp2 = pack2(b, b); }
    { float b = b_rel [h]; br2 = pack2(b, b); }
    const u64 neg1 = pack2(-1.f, -1.f);

    // this lane's pair indices (for the dist computation, lanes 0..20)
    const int li = (int)((PIp >> (3 * lane)) & 7);
    const int lj = (int)((PJp >> (3 * lane)) & 7);

    for (int g = blockIdx.x; g < G; g += GRID) {
        const int b0 = g * 4 + sub * 2;          // batches {b0, b0+1}
        const float* cb = ctx + b0;

        // ---- per-warp pair distances: lane p computes pair p (p < 21) ----
        u64 distp = 0;
        if (lane < NPAIR) {
            float2 eix = *(const float2*)(cb + (li * DE + 0) * B);
            float2 eiy = *(const float2*)(cb + (li * DE + 1) * B);
            float2 ejx = *(const float2*)(cb + (lj * DE + 0) * B);
            float2 ejy = *(const float2*)(cb + (lj * DE + 1) * B);
            float dxl = eix.x - ejx.x, dyl = eiy.x - ejy.x;
            float dxh = eix.y - ejx.y, dyh = eiy.y - ejy.y;
            distp = pack2(sqrt_approx(dxl*dxl + dyl*dyl),
                          sqrt_approx(dxh*dxh + dyh*dyh));
        }

        float* out0 = out + (size_t)b0 * ROW + h;
        float* out1 = out0 + ROW;                // batch b0+1

        // ---- per-entity: uniform LDG.64 ents -> prop embedding + q_e ----
        u64 qd[NE];
        #pragma unroll
        for (int e = 0; e < NE; e++) {
            float2 v0 = *(const float2*)(cb + (e * DE + 0) * B);
            float2 v1 = *(const float2*)(cb + (e * DE + 1) * B);
            float2 v2 = *(const float2*)(cb + (e * DE + 2) * B);
            float2 v3 = *(const float2*)(cb + (e * DE + 3) * B);
            u64 d0 = pack2(v0.x, v0.y);
            u64 d1 = pack2(v1.x, v1.y);
            u64 d2 = pack2(v2.x, v2.y);
            u64 d3 = pack2(v3.x, v3.y);
            // prop: relu(e . w_prop + b_prop)
            u64 acc = fma2(d0, wp2[0], bp2);
            acc = fma2(d1, wp2[1], acc);
            acc = fma2(d2, wp2[2], acc);
            acc = fma2(d3, wp2[3], acc);
            float lo, hi; unpack2(acc, lo, hi);
            out0[e * OUTC] = fmaxf(lo, 0.f);
            out1[e * OUTC] = fmaxf(hi, 0.f);
            // q_e = e . w_rel[0:4]
            u64 q = mul2(d0, wr2[0]);
            q = fma2(d1, wr2[1], q);
            q = fma2(d2, wr2[2], q);
            q = fma2(d3, wr2[3], q);
            qd[e] = q;
        }

        // ---- pairs: dist via shuffle, sum relu((q_i-q_j) + dist*w4 + b) ----
        u64 racc[NE];
        #pragma unroll
        for (int e = 0; e < NE; e++) racc[e] = 0ULL;

        #pragma unroll
        for (int p = 0; p < NPAIR; p++) {
            const int i = PI[p], j = PJ[p];
            u64 dist = shfl2(distp, p);
            u64 sb = fma2(dist, wr2[4], br2);    // symmetric part
            u64 sd = fma2(qd[j], neg1, qd[i]);   // q_i - q_j
            racc[i] = add2(racc[i], relu2(add2(sb, sd)));        // relu(sb + sd)
            racc[j] = add2(racc[j], relu2(fma2(sd, neg1, sb)));  // relu(sb - sd)
        }

        #pragma unroll
        for (int e = 0; e < NE; e++) {
            float lo, hi; unpack2(racc[e], lo, hi);
            out0[e * OUTC + H] = lo;
            out1[e * OUTC + H] = hi;
        }
    }
}

extern "C" void kernel_launch(void* const* d_in, const int* in_sizes, int n_in,
                              void* d_out, int out_size) {
    const float* ctx    = (const float*)d_in[0];
    const float* w_prop = (const float*)d_in[1];
    const float* b_prop = (const float*)d_in[2];
    const float* w_rel  = (const float*)d_in[3];
    const float* b_rel  = (const float*)d_in[4];
    float* out = (float*)d_out;

    const int B = in_sizes[0] / (NE * DE);   // 16384
    const int G = B / 4;                     // 4096 groups of 4 batches
    enc_kernel<<<GRID, 256>>>(ctx, w_prop, b_prop, w_rel, b_rel, out, B, G);
}

// round 14
// speedup vs baseline: 1.6147x; 1.6147x over previous
#include <cuda_runtime.h>

typedef unsigned long long u64;
typedef unsigned int u32;

__device__ __forceinline__ u64 pack2(float lo, float hi) {
    u64 r; asm("mov.b64 %0,{%1,%2};" : "=l"(r) : "f"(lo), "f"(hi)); return r;
}
__device__ __forceinline__ void unpack2(u64 v, float& lo, float& hi) {
    asm("mov.b64 {%0,%1}, %2;" : "=f"(lo), "=f"(hi) : "l"(v));
}
__device__ __forceinline__ u64 fma2(u64 a, u64 b, u64 c) {
    u64 d; asm("fma.rn.f32x2 %0,%1,%2,%3;" : "=l"(d) : "l"(a), "l"(b), "l"(c)); return d;
}
__device__ __forceinline__ u64 add2(u64 a, u64 b) {
    u64 d; asm("add.rn.f32x2 %0,%1,%2;" : "=l"(d) : "l"(a), "l"(b)); return d;
}
__device__ __forceinline__ u64 mul2(u64 a, u64 b) {
    u64 d; asm("mul.rn.f32x2 %0,%1,%2;" : "=l"(d) : "l"(a), "l"(b)); return d;
}
__device__ __forceinline__ float sqrt_approx(float x) {
    float r; asm("sqrt.approx.f32 %0, %1;" : "=f"(r) : "f"(x)); return r;
}
// relu both halves of a packed f32x2 (2 scalar FMNMX, alu pipe)
__device__ __forceinline__ u64 relu2(u64 v) {
    float lo, hi; unpack2(v, lo, hi);
    return pack2(fmaxf(lo, 0.f), fmaxf(hi, 0.f));
}

constexpr int NE = 7;      // entities
constexpr int DE = 4;      // dims per entity
constexpr int H  = 128;    // half embedding
constexpr int NPAIR = 21;  // unordered pairs
constexpr int OUTC = 2 * H;
constexpr int ROW = NE * OUTC;   // floats per batch element in out
constexpr int GRID = 592;        // 148 SMs x 4 resident CTAs = one wave

// pair index tables packed 3 bits/entry into u64 immediates (device-legal)
constexpr u64 pack_idx(const int* a) {
    u64 r = 0;
    for (int p = 0; p < NPAIR; p++) r |= (u64)a[p] << (3 * p);
    return r;
}
constexpr int PIa_host[NPAIR] = {0,0,0,0,0,0,1,1,1,1,1,2,2,2,2,3,3,3,4,4,5};
constexpr int PJa_host[NPAIR] = {1,2,3,4,5,6,2,3,4,5,6,3,4,5,6,4,5,6,5,6,6};
constexpr u64 PIp = pack_idx(PIa_host);
constexpr u64 PJp = pack_idx(PJa_host);

__global__ __launch_bounds__(256, 4)
void enc_kernel(const float* __restrict__ ctx,
                const float* __restrict__ w_prop, const float* __restrict__ b_prop,
                const float* __restrict__ w_rel,  const float* __restrict__ b_rel,
                float* __restrict__ out, int B, int G)
{
    constexpr int PI[NPAIR] = {0,0,0,0,0,0,1,1,1,1,1,2,2,2,2,3,3,3,4,4,5};
    constexpr int PJ[NPAIR] = {1,2,3,4,5,6,2,3,4,5,6,3,4,5,6,4,5,6,5,6,6};

    // two 128-thread sub-blocks per CTA; DOUBLE-BUFFERED shared state so
    // one barrier per iteration suffices (WAR ordered transitively).
    __shared__ __align__(16) u64 sh_ents[2][2][NE * DE];  // [parity][sub][row]
    __shared__ __align__(16) u64 sh_dist[2][2][NPAIR];

    const int tid  = threadIdx.x;
    const int lane = tid & 31;
    const int wid  = tid >> 5;
    const int s    = wid >> 2;           // sub-block 0/1
    const int h    = tid & 127;          // output column 0..127
    const int bar  = s + 1;              // named barrier id
    const bool w0  = (wid & 3) == 0;     // stage-1/2 warp of this sub-block

    // weights broadcast-packed once per CTA
    u64 wp2[DE], wr2[DE + 1], bp2, br2;
    #pragma unroll
    for (int d = 0; d < DE; d++)     { float w = w_prop[d * H + h]; wp2[d] = pack2(w, w); }
    #pragma unroll
    for (int d = 0; d < DE + 1; d++) { float w = w_rel [d * H + h]; wr2[d] = pack2(w, w); }
    { float b = b_prop[h]; bp2 = pack2(b, b); }
    { float b = b_rel [h]; br2 = pack2(b, b); }
    const u64 neg1 = pack2(-1.f, -1.f);

    // warp-0 dist-lane pair indices (lanes 0..20; harmless defaults elsewhere)
    const int li4 = (int)((PIp >> (3 * lane)) & 7) * DE;
    const int lj4 = (int)((PJp >> (3 * lane)) & 7) * DE;

    // prefetch first group's ctx rows (warp 0 lanes 0..27)
    int g = blockIdx.x;
    float2 v = make_float2(0.f, 0.f);
    if (w0 && lane < NE * DE && g < G)
        v = *(const float2*)(ctx + lane * B + (g * 4 + s * 2));

    int par = 0;
    for (; g < G; g += GRID) {
        const int b0 = g * 4 + s * 2;

        if (w0) {
            // ---- stage 1: commit prefetched ctx rows to shared ----
            if (lane < NE * DE) sh_ents[par][s][lane] = pack2(v.x, v.y);
            // ---- stage 2: dist via intra-warp shfl of register-held rows ----
            // (8 SHFL instructions for the whole warp; no shared read)
            float xi_l = __shfl_sync(0xffffffffu, v.x, li4 + 0);
            float xi_h = __shfl_sync(0xffffffffu, v.y, li4 + 0);
            float yi_l = __shfl_sync(0xffffffffu, v.x, li4 + 1);
            float yi_h = __shfl_sync(0xffffffffu, v.y, li4 + 1);
            float xj_l = __shfl_sync(0xffffffffu, v.x, lj4 + 0);
            float xj_h = __shfl_sync(0xffffffffu, v.y, lj4 + 0);
            float yj_l = __shfl_sync(0xffffffffu, v.x, lj4 + 1);
            float yj_h = __shfl_sync(0xffffffffu, v.y, lj4 + 1);
            if (lane < NPAIR) {
                float dxl = xi_l - xj_l, dyl = yi_l - yj_l;
                float dxh = xi_h - xj_h, dyh = yi_h - yj_h;
                sh_dist[par][s][lane] = pack2(sqrt_approx(dxl*dxl + dyl*dyl),
                                              sqrt_approx(dxh*dxh + dyh*dyh));
            }
            // prefetch next group's rows (latency covered by stage 3)
            const int gn = g + GRID;
            if (lane < NE * DE && gn < G)
                v = *(const float2*)(ctx + lane * B + (gn * 4 + s * 2));
        }
        asm volatile("bar.sync %0, 128;" :: "r"(bar) : "memory");

        // ---- stage 3: packed-f32x2 compute, one h per thread ----
        float* out0 = out + (size_t)b0 * ROW;
        float* out1 = out0 + ROW;     // batch b0+1

        u64 qd[NE];
        const ulonglong2* e4 = (const ulonglong2*)sh_ents[par][s];
        #pragma unroll
        for (int e = 0; e < NE; e++) {
            ulonglong2 q0 = e4[e*2 + 0];   // d0, d1 (packed over 2 batches)
            ulonglong2 q1 = e4[e*2 + 1];   // d2, d3
            u64 acc = fma2(q0.x, wp2[0], bp2);
            acc = fma2(q0.y, wp2[1], acc);
            acc = fma2(q1.x, wp2[2], acc);
            acc = fma2(q1.y, wp2[3], acc);
            float lo, hi; unpack2(acc, lo, hi);
            out0[e * OUTC + h] = fmaxf(lo, 0.f);
            out1[e * OUTC + h] = fmaxf(hi, 0.f);
            u64 q = mul2(q0.x, wr2[0]);
            q = fma2(q0.y, wr2[1], q);
            q = fma2(q1.x, wr2[2], q);
            q = fma2(q1.y, wr2[3], q);
            qd[e] = q;
        }

        u64 racc[NE];
        #pragma unroll
        for (int e = 0; e < NE; e++) racc[e] = 0ULL;

        const u64* db = sh_dist[par][s];
        #pragma unroll
        for (int p = 0; p < NPAIR; p++) {
            const int i = PI[p], j = PJ[p];
            u64 sb = fma2(db[p], wr2[4], br2);   // symmetric part
            u64 sd = fma2(qd[j], neg1, qd[i]);   // q_i - q_j
            racc[i] = add2(racc[i], relu2(add2(sb, sd)));        // relu(sb + sd)
            racc[j] = add2(racc[j], relu2(fma2(sd, neg1, sb)));  // relu(sb - sd)
        }

        #pragma unroll
        for (int e = 0; e < NE; e++) {
            float lo, hi; unpack2(racc[e], lo, hi);
            out0[e * OUTC + H + h] = lo;
            out1[e * OUTC + H + h] = hi;
        }

        par ^= 1;   // double-buffer flip: no trailing WAR barrier needed
    }
}

extern "C" void kernel_launch(void* const* d_in, const int* in_sizes, int n_in,
                              void* d_out, int out_size) {
    const float* ctx    = (const float*)d_in[0];
    const float* w_prop = (const float*)d_in[1];
    const float* b_prop = (const float*)d_in[2];
    const float* w_rel  = (const float*)d_in[3];
    const float* b_rel  = (const float*)d_in[4];
    float* out = (float*)d_out;

    const int B = in_sizes[0] / (NE * DE);   // 16384
    const int G = B / 4;                     // 4096 groups of 4 batches
    enc_kernel<<<GRID, 256>>>(ctx, w_prop, b_prop, w_rel, b_rel, out, B, G);
}

// round 15
// speedup vs baseline: 1.6539x; 1.0243x over previous
#include <cuda_runtime.h>

typedef unsigned long long u64;
typedef unsigned int u32;

__device__ __forceinline__ u64 pack2(float lo, float hi) {
    u64 r; asm("mov.b64 %0,{%1,%2};" : "=l"(r) : "f"(lo), "f"(hi)); return r;
}
__device__ __forceinline__ void unpack2(u64 v, float& lo, float& hi) {
    asm("mov.b64 {%0,%1}, %2;" : "=f"(lo), "=f"(hi) : "l"(v));
}
__device__ __forceinline__ u64 fma2(u64 a, u64 b, u64 c) {
    u64 d; asm("fma.rn.f32x2 %0,%1,%2,%3;" : "=l"(d) : "l"(a), "l"(b), "l"(c)); return d;
}
__device__ __forceinline__ u64 add2(u64 a, u64 b) {
    u64 d; asm("add.rn.f32x2 %0,%1,%2;" : "=l"(d) : "l"(a), "l"(b)); return d;
}
__device__ __forceinline__ u64 mul2(u64 a, u64 b) {
    u64 d; asm("mul.rn.f32x2 %0,%1,%2;" : "=l"(d) : "l"(a), "l"(b)); return d;
}
__device__ __forceinline__ float sqrt_approx(float x) {
    float r; asm("sqrt.approx.f32 %0, %1;" : "=f"(r) : "f"(x)); return r;
}
// relu both halves of a packed f32x2 (2 scalar FMNMX, alu pipe)
__device__ __forceinline__ u64 relu2(u64 v) {
    float lo, hi; unpack2(v, lo, hi);
    return pack2(fmaxf(lo, 0.f), fmaxf(hi, 0.f));
}

constexpr int NE = 7;      // entities
constexpr int DE = 4;      // dims per entity
constexpr int H  = 128;    // half embedding
constexpr int NPAIR = 21;  // unordered pairs
constexpr int OUTC = 2 * H;
constexpr int ROW = NE * OUTC;   // floats per batch element in out
constexpr int GRID = 592;        // 148 SMs x 4 resident CTAs = one wave

// pair index tables packed 3 bits/entry into u64 immediates (device-legal)
constexpr u64 pack_idx(const int* a) {
    u64 r = 0;
    for (int p = 0; p < NPAIR; p++) r |= (u64)a[p] << (3 * p);
    return r;
}
constexpr int PIa_host[NPAIR] = {0,0,0,0,0,0,1,1,1,1,1,2,2,2,2,3,3,3,4,4,5};
constexpr int PJa_host[NPAIR] = {1,2,3,4,5,6,2,3,4,5,6,3,4,5,6,4,5,6,5,6,6};
constexpr u64 PIp = pack_idx(PIa_host);
constexpr u64 PJp = pack_idx(PJa_host);

__global__ __launch_bounds__(256, 4)
void enc_kernel(const float* __restrict__ ctx,
                const float* __restrict__ w_prop, const float* __restrict__ b_prop,
                const float* __restrict__ w_rel,  const float* __restrict__ b_rel,
                float* __restrict__ out, int B, int G)
{
    constexpr int PI[NPAIR] = {0,0,0,0,0,0,1,1,1,1,1,2,2,2,2,3,3,3,4,4,5};
    constexpr int PJ[NPAIR] = {1,2,3,4,5,6,2,3,4,5,6,3,4,5,6,4,5,6,5,6,6};

    // two 128-thread sub-blocks per CTA; DOUBLE-BUFFERED shared state so
    // one barrier per iteration suffices. sh_dist padded to 22 for 16B align.
    __shared__ __align__(16) u64 sh_ents[2][2][NE * DE];  // [parity][sub][row]
    __shared__ __align__(16) u64 sh_dist[2][2][22];

    const int tid  = threadIdx.x;
    const int lane = tid & 31;
    const int wid  = tid >> 5;
    const int s    = wid >> 2;           // sub-block 0/1
    const int h    = tid & 127;          // output column 0..127
    const int bar  = s + 1;              // named barrier id
    const int wrole = wid & 3;           // 0: ents loader, 1: dist builder
    const bool w0  = wrole == 0;
    const bool w1  = wrole == 1;

    // weights broadcast-packed once per CTA
    u64 wp2[DE], wr2[DE + 1], bp2, br2;
    #pragma unroll
    for (int d = 0; d < DE; d++)     { float w = w_prop[d * H + h]; wp2[d] = pack2(w, w); }
    #pragma unroll
    for (int d = 0; d < DE + 1; d++) { float w = w_rel [d * H + h]; wr2[d] = pack2(w, w); }
    { float b = b_prop[h]; bp2 = pack2(b, b); }
    { float b = b_rel [h]; br2 = pack2(b, b); }
    const u64 neg1 = pack2(-1.f, -1.f);

    // w1 dist-lane pair row indices (lanes 0..20)
    const int li4 = (int)((PIp >> (3 * lane)) & 7) * DE;
    const int lj4 = (int)((PJp >> (3 * lane)) & 7) * DE;

    // w0 prefetch of first group's ctx rows (lanes 0..27)
    int g = blockIdx.x;
    float2 v = make_float2(0.f, 0.f);
    if (w0 && lane < NE * DE && g < G)
        v = *(const float2*)(ctx + lane * B + (g * 4 + s * 2));

    int par = 0;
    for (; g < G; g += GRID) {
        const int b0 = g * 4 + s * 2;
        const float* cb = ctx + b0;

        if (w0) {
            // commit prefetched ctx rows; prefetch next group
            if (lane < NE * DE) sh_ents[par][s][lane] = pack2(v.x, v.y);
            const int gn = g + GRID;
            if (lane < NE * DE && gn < G)
                v = *(const float2*)(ctx + lane * B + (gn * 4 + s * 2));
        } else if (w1 && lane < NPAIR) {
            // dist builder: 4 coord rows are L1-hits (w0 prefetched the lines)
            float2 xi = *(const float2*)(cb + (li4    ) * B);
            float2 yi = *(const float2*)(cb + (li4 + 1) * B);
            float2 xj = *(const float2*)(cb + (lj4    ) * B);
            float2 yj = *(const float2*)(cb + (lj4 + 1) * B);
            float dxl = xi.x - xj.x, dyl = yi.x - yj.x;
            float dxh = xi.y - xj.y, dyh = yi.y - yj.y;
            sh_dist[par][s][lane] = pack2(sqrt_approx(dxl*dxl + dyl*dyl),
                                          sqrt_approx(dxh*dxh + dyh*dyh));
        }
        asm volatile("bar.sync %0, 128;" :: "r"(bar) : "memory");

        // ---- stage 3: packed-f32x2 compute, one h per thread ----
        float* out0 = out + (size_t)b0 * ROW;
        float* out1 = out0 + ROW;     // batch b0+1

        u64 qd[NE];
        const ulonglong2* e4 = (const ulonglong2*)sh_ents[par][s];
        #pragma unroll
        for (int e = 0; e < NE; e++) {
            ulonglong2 q0 = e4[e*2 + 0];   // d0, d1 (packed over 2 batches)
            ulonglong2 q1 = e4[e*2 + 1];   // d2, d3
            u64 acc = fma2(q0.x, wp2[0], bp2);
            acc = fma2(q0.y, wp2[1], acc);
            acc = fma2(q1.x, wp2[2], acc);
            acc = fma2(q1.y, wp2[3], acc);
            float lo, hi; unpack2(acc, lo, hi);
            out0[e * OUTC + h] = fmaxf(lo, 0.f);
            out1[e * OUTC + h] = fmaxf(hi, 0.f);
            u64 q = mul2(q0.x, wr2[0]);
            q = fma2(q0.y, wr2[1], q);
            q = fma2(q1.x, wr2[2], q);
            q = fma2(q1.y, wr2[3], q);
            qd[e] = q;
        }

        // relation embedding; first-touch init avoids zeroing racc
        u64 racc[NE];
        const u64* db = sh_dist[par][s];

        auto do_pair = [&](int p, u64 dist) {
            const int i = PI[p], j = PJ[p];
            u64 sb = fma2(dist, wr2[4], br2);    // symmetric part
            u64 sd = fma2(qd[j], neg1, qd[i]);   // q_i - q_j
            u64 rij = relu2(add2(sb, sd));       // relu(sb + sd)
            u64 rji = relu2(fma2(sd, neg1, sb)); // relu(sb - sd)
            if (p == 0) racc[i] = rij; else racc[i] = add2(racc[i], rij);
            if (p <= 5) racc[j] = rji; else racc[j] = add2(racc[j], rji);
        };

        #pragma unroll
        for (int pp = 0; pp < 20; pp += 2) {
            ulonglong2 dd = *(const ulonglong2*)(db + pp);   // LDS.128
            do_pair(pp,     dd.x);
            do_pair(pp + 1, dd.y);
        }
        do_pair(20, db[20]);

        #pragma unroll
        for (int e = 0; e < NE; e++) {
            float lo, hi; unpack2(racc[e], lo, hi);
            out0[e * OUTC + H + h] = lo;
            out1[e * OUTC + H + h] = hi;
        }

        par ^= 1;   // double-buffer flip: no trailing WAR barrier needed
    }
}

extern "C" void kernel_launch(void* const* d_in, const int* in_sizes, int n_in,
                              void* d_out, int out_size) {
    const float* ctx    = (const float*)d_in[0];
    const float* w_prop = (const float*)d_in[1];
    const float* b_prop = (const float*)d_in[2];
    const float* w_rel  = (const float*)d_in[3];
    const float* b_rel  = (const float*)d_in[4];
    float* out = (float*)d_out;

    const int B = in_sizes[0] / (NE * DE);   // 16384
    const int G = B / 4;                     // 4096 groups of 4 batches
    enc_kernel<<<GRID, 256>>>(ctx, w_prop, b_prop, w_rel, b_rel, out, B, G);
}